// round 6
// baseline (speedup 1.0000x reference)
#include <cuda_runtime.h>
#include <cuda_fp16.h>

#define MAXN 100000
#define MAXE 1600000

// ---------------- scratch (device globals; no allocation allowed) ----------------
__device__ float d_h[MAXN * 64];        // node features buffer A
__device__ float d_h2[MAXN * 64];       // node features buffer B (double buffer)
__device__ __half2 d_g2[MAXN * 32];     // GAT features, packed {g[t], g[t+32]} per lane
__device__ float d_as[MAXN * 4];        // attention src logits per head
__device__ float d_ad[MAXN * 4];        // attention dst logits per head
__device__ float d_dinv[MAXN];
__device__ float d_Wc[3 * 64 * 64];     // fus_W_left @ e8_W, layout [layer][j][k]

// CSR: slots [0,N) = by-row (E8, neighbor=col), slots [N,2N) = by-col (GAT, neighbor=src)
__device__ int d_cnt[2 * MAXN];
__device__ int d_off[2 * MAXN];
__device__ int d_cur[2 * MAXN];
__device__ int d_total;
__device__ int d_adj[2 * MAXE];

__device__ __forceinline__ float leaky02(float x) { return x > 0.f ? x : 0.2f * x; }

// ---------------- CSR build ----------------
__global__ void zero_cnt_kernel(int n2) {
    int i = blockIdx.x * blockDim.x + threadIdx.x;
    if (i < n2) d_cnt[i] = 0;
    if (i == 0) d_total = 0;
}

__global__ void count_kernel(const int* __restrict__ ei, int E, int n) {
    int e = blockIdx.x * blockDim.x + threadIdx.x;
    if (e < E) {
        atomicAdd(&d_cnt[ei[e]], 1);           // by row
        atomicAdd(&d_cnt[n + ei[E + e]], 1);   // by col
    }
}

__global__ void alloc_kernel(int n2) {
    int i = blockIdx.x * blockDim.x + threadIdx.x;
    if (i < n2) {
        int c = d_cnt[i];
        int o = atomicAdd(&d_total, c);
        d_off[i] = o;
        d_cur[i] = o;
    }
}

__global__ void fill_kernel(const int* __restrict__ ei, int E, int n) {
    int e = blockIdx.x * blockDim.x + threadIdx.x;
    if (e < E) {
        int r = ei[e], c = ei[E + e];
        int p = atomicAdd(&d_cur[r], 1);
        d_adj[p] = c;
        int p2 = atomicAdd(&d_cur[n + c], 1);
        d_adj[p2] = r;
    }
}

// ---------------- nodeprep: dinv + emb + n1(layer0) + Wc ----------------
__global__ void __launch_bounds__(256) nodeprep_kernel(
        const float* __restrict__ x, const float* __restrict__ embW,
        const float* __restrict__ embB, const float* __restrict__ gatW,
        const float* __restrict__ attS, const float* __restrict__ attD,
        const float* __restrict__ fusW, const float* __restrict__ e8W,
        int ngrid, int n) {
    if (blockIdx.x >= (unsigned)ngrid) {
        int bid = blockIdx.x - ngrid;
        int gidx = bid * 256 + threadIdx.x;
        if (gidx < 3 * 4096) {
            int layer = gidx >> 12;
            int idx = gidx & 4095;
            int j = idx >> 6, k = idx & 63;
            const float* F = fusW + layer * 64 * 128;
            const float* Ew = e8W + layer * 64 * 64;
            float acc = 0.f;
#pragma unroll
            for (int m = 0; m < 64; m++) acc += F[j * 128 + m] * Ew[m * 64 + k];
            d_Wc[layer * 4096 + j * 64 + k] = acc;
        }
        return;
    }
    __shared__ float We[64 * 65];
    __shared__ float Wg[64 * 65];
    __shared__ float bs[64];
    for (int idx = threadIdx.x; idx < 4096; idx += blockDim.x) {
        int j = idx >> 6, k = idx & 63;
        We[j * 65 + k] = embW[idx];
        Wg[k * 65 + j] = gatW[idx];
    }
    if (threadIdx.x < 64) bs[threadIdx.x] = embB[threadIdx.x];
    __syncthreads();
    int warp = threadIdx.x >> 5, t = threadIdx.x & 31;
    float as0 = attS[t], as1 = attS[t + 32];
    float ad0 = attD[t], ad1 = attD[t + 32];
    for (int node = blockIdx.x * 8 + warp; node < n; node += ngrid * 8) {
        if (t == 0) {
            float dg = (float)d_cnt[n + node];
            d_dinv[node] = dg > 0.f ? rsqrtf(dg) : 0.f;
        }
        float in0 = x[node * 64 + t];
        float in1 = x[node * 64 + t + 32];
        float h0 = bs[t], h1 = bs[t + 32];
#pragma unroll
        for (int k = 0; k < 32; k++) {
            float xk = __shfl_sync(0xffffffffu, in0, k);
            h0 += xk * We[t * 65 + k];
            h1 += xk * We[(t + 32) * 65 + k];
        }
#pragma unroll
        for (int k = 0; k < 32; k++) {
            float xk = __shfl_sync(0xffffffffu, in1, k);
            h0 += xk * We[t * 65 + 32 + k];
            h1 += xk * We[(t + 32) * 65 + 32 + k];
        }
        d_h[node * 64 + t] = h0;
        d_h[node * 64 + t + 32] = h1;
        float g0 = 0.f, g1 = 0.f;
#pragma unroll
        for (int k = 0; k < 32; k++) {
            float xk = __shfl_sync(0xffffffffu, h0, k);
            g0 += xk * Wg[t * 65 + k];
            g1 += xk * Wg[(t + 32) * 65 + k];
        }
#pragma unroll
        for (int k = 0; k < 32; k++) {
            float xk = __shfl_sync(0xffffffffu, h1, k);
            g0 += xk * Wg[t * 65 + 32 + k];
            g1 += xk * Wg[(t + 32) * 65 + 32 + k];
        }
        d_g2[node * 32 + t] = __floats2half2_rn(g0, g1);
        float ps0 = g0 * as0, ps1 = g1 * as1;
        float pd0 = g0 * ad0, pd1 = g1 * ad1;
#pragma unroll
        for (int off = 8; off; off >>= 1) {
            ps0 += __shfl_xor_sync(0xffffffffu, ps0, off);
            ps1 += __shfl_xor_sync(0xffffffffu, ps1, off);
            pd0 += __shfl_xor_sync(0xffffffffu, pd0, off);
            pd1 += __shfl_xor_sync(0xffffffffu, pd1, off);
        }
        if ((t & 15) == 0) {
            int hh = t >> 4;
            d_as[node * 4 + hh] = ps0;
            d_as[node * 4 + 2 + hh] = ps1;
            d_ad[node * 4 + hh] = pd0;
            d_ad[node * 4 + 2 + hh] = pd1;
        }
    }
}

// ---------------- N1 (layers 1,2): 4-node batched GEMV ----------------
__global__ void __launch_bounds__(256) n1_kernel(
        const float* __restrict__ gatW, const float* __restrict__ attS,
        const float* __restrict__ attD, int layer, int flip, int n) {
    const float* hin = flip ? d_h2 : d_h;
    __shared__ float Ws[64 * 65];
    const float* W = gatW + layer * 4096;
    for (int idx = threadIdx.x; idx < 4096; idx += blockDim.x) {
        int k = idx >> 6, j = idx & 63;
        Ws[j * 65 + k] = W[idx];
    }
    __syncthreads();
    int warp = threadIdx.x >> 5, t = threadIdx.x & 31;
    float as0 = attS[layer * 64 + t], as1 = attS[layer * 64 + t + 32];
    float ad0 = attD[layer * 64 + t], ad1 = attD[layer * 64 + t + 32];
    int gw = blockIdx.x * 8 + warp;
    int totw = gridDim.x * 8;
    for (int nb = gw * 4; nb < n; nb += totw * 4) {
        float in0[4], in1[4];
#pragma unroll
        for (int q = 0; q < 4; q++) {
            int node = nb + q;
            in0[q] = node < n ? hin[node * 64 + t] : 0.f;
            in1[q] = node < n ? hin[node * 64 + t + 32] : 0.f;
        }
        float g0[4] = {0.f, 0.f, 0.f, 0.f}, g1[4] = {0.f, 0.f, 0.f, 0.f};
#pragma unroll
        for (int k = 0; k < 32; k++) {
            float wa = Ws[t * 65 + k], wb = Ws[(t + 32) * 65 + k];
#pragma unroll
            for (int q = 0; q < 4; q++) {
                float xk = __shfl_sync(0xffffffffu, in0[q], k);
                g0[q] += xk * wa;
                g1[q] += xk * wb;
            }
        }
#pragma unroll
        for (int k = 0; k < 32; k++) {
            float wa = Ws[t * 65 + 32 + k], wb = Ws[(t + 32) * 65 + 32 + k];
#pragma unroll
            for (int q = 0; q < 4; q++) {
                float xk = __shfl_sync(0xffffffffu, in1[q], k);
                g0[q] += xk * wa;
                g1[q] += xk * wb;
            }
        }
#pragma unroll
        for (int q = 0; q < 4; q++) {
            int node = nb + q;
            if (node >= n) break;
            d_g2[node * 32 + t] = __floats2half2_rn(g0[q], g1[q]);
            float ps0 = g0[q] * as0, ps1 = g1[q] * as1;
            float pd0 = g0[q] * ad0, pd1 = g1[q] * ad1;
#pragma unroll
            for (int off = 8; off; off >>= 1) {
                ps0 += __shfl_xor_sync(0xffffffffu, ps0, off);
                ps1 += __shfl_xor_sync(0xffffffffu, ps1, off);
                pd0 += __shfl_xor_sync(0xffffffffu, pd0, off);
                pd1 += __shfl_xor_sync(0xffffffffu, pd1, off);
            }
            if ((t & 15) == 0) {
                int hh = t >> 4;
                d_as[node * 4 + hh] = ps0;
                d_as[node * 4 + 2 + hh] = ps1;
                d_ad[node * 4 + hh] = pd0;
                d_ad[node * 4 + 2 + hh] = pd1;
            }
        }
    }
}

// ---------------- fused layer: gathers + 4-node batched GEMVs + LN ----------------
__global__ void __launch_bounds__(256) layer_kernel(
        const float* __restrict__ fusW, const float* __restrict__ fusB,
        const float* __restrict__ gatB, const float* __restrict__ lnG,
        const float* __restrict__ lnB, int layer, int flip, int n) {
    const float* hin = flip ? d_h2 : d_h;
    float* hout = flip ? d_h : d_h2;
    __shared__ float W1s[64 * 65];
    __shared__ float W2s[64 * 65];
    __shared__ float fb[64], gb[64], lg[64], lb[64];
    const float* Wc = d_Wc + layer * 4096;
    const float* F = fusW + layer * 64 * 128;
    for (int idx = threadIdx.x; idx < 4096; idx += blockDim.x) {
        int j = idx >> 6, k = idx & 63;
        W1s[j * 65 + k] = Wc[idx];
        W2s[j * 65 + k] = F[j * 128 + 64 + k];
    }
    if (threadIdx.x < 64) {
        fb[threadIdx.x] = fusB[layer * 64 + threadIdx.x];
        gb[threadIdx.x] = gatB[layer * 64 + threadIdx.x];
        lg[threadIdx.x] = lnG[layer * 64 + threadIdx.x];
        lb[threadIdx.x] = lnB[layer * 64 + threadIdx.x];
    }
    __syncthreads();
    int warp = threadIdx.x >> 5, t = threadIdx.x & 31;
    int hA = t >> 4, hB = 2 + (t >> 4);
    int gw = blockIdx.x * 8 + warp;
    int totw = gridDim.x * 8;

    for (int nb = gw * 4; nb < n; nb += totw * 4) {
        float a0[4], a1[4], x0[4], x1[4];
#pragma unroll
        for (int q = 0; q < 4; q++) {
            int node = nb + q;
            if (node >= n) { a0[q] = a1[q] = x0[q] = x1[q] = 0.f; continue; }
            // --- GAT gather (col-CSR) ---
            float adA = d_ad[node * 4 + hA];
            float adB = d_ad[node * 4 + hB];
            float eeS0 = __expf(leaky02(d_as[node * 4 + hA] + adA));
            float eeS1 = __expf(leaky02(d_as[node * 4 + hB] + adB));
            float2 gself = __half22float2(d_g2[node * 32 + t]);
            float w0 = eeS0 * gself.x;
            float w1 = eeS1 * gself.y;
            float s0 = eeS0, s1 = eeS1;
            {
                int beg = d_off[n + node];
                int dc = d_cnt[n + node];
                for (int i = 0; i < dc; i++) {
                    int src = __ldg(&d_adj[beg + i]);
                    float2 gv = __half22float2(d_g2[src * 32 + t]);
                    float ee0 = __expf(leaky02(d_as[src * 4 + hA] + adA));
                    float ee1 = __expf(leaky02(d_as[src * 4 + hB] + adB));
                    w0 += ee0 * gv.x;
                    w1 += ee1 * gv.y;
                    s0 += ee0;
                    s1 += ee1;
                }
            }
            x0[q] = w0 / s0 + gb[t];
            x1[q] = w1 / s1 + gb[t + 32];
            // --- E8 gather (row-CSR) ---
            float e0 = 0.f, e1 = 0.f;
            {
                int beg = d_off[node];
                int dr = d_cnt[node];
                for (int i = 0; i < dr; i++) {
                    int c = __ldg(&d_adj[beg + i]);
                    float dv = d_dinv[c];
                    e0 += dv * hin[c * 64 + t];
                    e1 += dv * hin[c * 64 + t + 32];
                }
                float dvr = d_dinv[node];
                e0 *= dvr;
                e1 *= dvr;
            }
            a0[q] = e0;
            a1[q] = e1;
        }

        // --- batched GEMVs ---
        float acc0[4], acc1[4];
#pragma unroll
        for (int q = 0; q < 4; q++) { acc0[q] = fb[t]; acc1[q] = fb[t + 32]; }
#pragma unroll
        for (int k = 0; k < 32; k++) {
            float wa = W1s[t * 65 + k], wb = W1s[(t + 32) * 65 + k];
#pragma unroll
            for (int q = 0; q < 4; q++) {
                float ak = __shfl_sync(0xffffffffu, a0[q], k);
                acc0[q] += ak * wa;
                acc1[q] += ak * wb;
            }
        }
#pragma unroll
        for (int k = 0; k < 32; k++) {
            float wa = W1s[t * 65 + 32 + k], wb = W1s[(t + 32) * 65 + 32 + k];
#pragma unroll
            for (int q = 0; q < 4; q++) {
                float ak = __shfl_sync(0xffffffffu, a1[q], k);
                acc0[q] += ak * wa;
                acc1[q] += ak * wb;
            }
        }
#pragma unroll
        for (int k = 0; k < 32; k++) {
            float wa = W2s[t * 65 + k], wb = W2s[(t + 32) * 65 + k];
#pragma unroll
            for (int q = 0; q < 4; q++) {
                float xk = __shfl_sync(0xffffffffu, x0[q], k);
                acc0[q] += xk * wa;
                acc1[q] += xk * wb;
            }
        }
#pragma unroll
        for (int k = 0; k < 32; k++) {
            float wa = W2s[t * 65 + 32 + k], wb = W2s[(t + 32) * 65 + 32 + k];
#pragma unroll
            for (int q = 0; q < 4; q++) {
                float xk = __shfl_sync(0xffffffffu, x1[q], k);
                acc0[q] += xk * wa;
                acc1[q] += xk * wb;
            }
        }

        // --- residual + LN + ReLU + store, per node ---
#pragma unroll
        for (int q = 0; q < 4; q++) {
            int node = nb + q;
            if (node >= n) break;
            float c0 = acc0[q] + hin[node * 64 + t];
            float c1 = acc1[q] + hin[node * 64 + t + 32];
            float ssum = c0 + c1;
#pragma unroll
            for (int off = 16; off; off >>= 1) ssum += __shfl_xor_sync(0xffffffffu, ssum, off);
            float mu = ssum * (1.f / 64.f);
            float dd0 = c0 - mu, dd1 = c1 - mu;
            float vs = dd0 * dd0 + dd1 * dd1;
#pragma unroll
            for (int off = 16; off; off >>= 1) vs += __shfl_xor_sync(0xffffffffu, vs, off);
            float rstd = rsqrtf(vs * (1.f / 64.f) + 1e-5f);
            hout[node * 64 + t] = fmaxf(dd0 * rstd * lg[t] + lb[t], 0.f);
            hout[node * 64 + t + 32] = fmaxf(dd1 * rstd * lg[t + 32] + lb[t + 32], 0.f);
        }
    }
}

// ---------------- readout ----------------
__global__ void readout_kernel(const float* __restrict__ rW1, const float* __restrict__ rb1,
                               const float* __restrict__ rW2, const float* __restrict__ rb2,
                               float* __restrict__ out, int n) {
    const float* hin = d_h2;
    __shared__ float W1s[32 * 65];
    __shared__ float b1s[32], W2s[32];
    for (int idx = threadIdx.x; idx < 2048; idx += blockDim.x) {
        int m = idx >> 6, k = idx & 63;
        W1s[m * 65 + k] = rW1[idx];
    }
    if (threadIdx.x < 32) {
        b1s[threadIdx.x] = rb1[threadIdx.x];
        W2s[threadIdx.x] = rW2[threadIdx.x];
    }
    __syncthreads();
    float b2 = rb2[0];
    int warp = threadIdx.x >> 5, t = threadIdx.x & 31;
    for (int node = blockIdx.x * 8 + warp; node < n; node += gridDim.x * 8) {
        float in0 = hin[node * 64 + t], in1 = hin[node * 64 + t + 32];
        float acc = b1s[t];
#pragma unroll
        for (int k = 0; k < 32; k++) {
            float xk = __shfl_sync(0xffffffffu, in0, k);
            acc += xk * W1s[t * 65 + k];
        }
#pragma unroll
        for (int k = 0; k < 32; k++) {
            float xk = __shfl_sync(0xffffffffu, in1, k);
            acc += xk * W1s[t * 65 + 32 + k];
        }
        acc = fmaxf(acc, 0.f);
        float p = acc * W2s[t];
#pragma unroll
        for (int off = 16; off; off >>= 1) p += __shfl_xor_sync(0xffffffffu, p, off);
        if (t == 0) out[node] = 1.f / (1.f + __expf(-(p + b2)));
    }
}

// ---------------- launch ----------------
extern "C" void kernel_launch(void* const* d_in, const int* in_sizes, int n_in,
                              void* d_out, int out_size) {
    const float* x    = (const float*)d_in[0];
    const int*   ei   = (const int*)d_in[1];
    const float* embW = (const float*)d_in[2];
    const float* embB = (const float*)d_in[3];
    const float* e8W  = (const float*)d_in[4];
    const float* gatW = (const float*)d_in[5];
    const float* attS = (const float*)d_in[6];
    const float* attD = (const float*)d_in[7];
    const float* gatB = (const float*)d_in[8];
    const float* fusW = (const float*)d_in[9];
    const float* fusB = (const float*)d_in[10];
    const float* lnG  = (const float*)d_in[11];
    const float* lnB  = (const float*)d_in[12];
    const float* rW1  = (const float*)d_in[13];
    const float* rb1  = (const float*)d_in[14];
    const float* rW2  = (const float*)d_in[15];
    const float* rb2  = (const float*)d_in[16];
    float* out = (float*)d_out;

    int n = in_sizes[0] / 64;
    int E = in_sizes[1] / 2;
    int n2 = 2 * n;
    int ngrid = 1563;

    zero_cnt_kernel<<<(n2 + 255) / 256, 256>>>(n2);
    count_kernel<<<(E + 255) / 256, 256>>>(ei, E, n);
    alloc_kernel<<<(n2 + 255) / 256, 256>>>(n2);
    fill_kernel<<<(E + 255) / 256, 256>>>(ei, E, n);
    nodeprep_kernel<<<ngrid + 48, 256>>>(x, embW, embB, gatW, attS, attD, fusW, e8W, ngrid, n);
    layer_kernel<<<ngrid, 256>>>(fusW, fusB, gatB, lnG, lnB, 0, 0, n);
    for (int l = 1; l < 3; l++) {
        int flip = l & 1;
        n1_kernel<<<ngrid, 256>>>(gatW, attS, attD, l, flip, n);
        layer_kernel<<<ngrid, 256>>>(fusW, fusB, gatB, lnG, lnB, l, flip, n);
    }
    readout_kernel<<<ngrid, 256>>>(rW1, rb1, rW2, rb2, out, n);
}

// round 7
// speedup vs baseline: 1.0647x; 1.0647x over previous
#include <cuda_runtime.h>
#include <cuda_fp16.h>

#define MAXN 100000
#define MAXE 1600000

// ---------------- scratch ----------------
__device__ float d_h[MAXN * 64];
__device__ float d_h2[MAXN * 64];
__device__ __half2 d_g2[MAXN * 32];     // {g[t], g[t+32]} per lane
__device__ float d_as[MAXN * 4];
__device__ float d_ad[MAXN * 4];
__device__ float d_dinv[MAXN];
__device__ float d_Wc[3 * 64 * 64];

__device__ int d_cnt[2 * MAXN];
__device__ int d_off[2 * MAXN];
__device__ int d_cur[2 * MAXN];
__device__ int d_total;
__device__ int d_adj[2 * MAXE];

__device__ __forceinline__ float leaky02(float x) { return x > 0.f ? x : 0.2f * x; }

// ---------------- CSR build ----------------
__global__ void zero_cnt_kernel(int n2) {
    int i = blockIdx.x * blockDim.x + threadIdx.x;
    if (i < n2) d_cnt[i] = 0;
    if (i == 0) d_total = 0;
}

__global__ void count_kernel(const int* __restrict__ ei, int E, int n) {
    int e = blockIdx.x * blockDim.x + threadIdx.x;
    if (e < E) {
        atomicAdd(&d_cnt[ei[e]], 1);
        atomicAdd(&d_cnt[n + ei[E + e]], 1);
    }
}

__global__ void alloc_kernel(int n2) {
    int i = blockIdx.x * blockDim.x + threadIdx.x;
    if (i < n2) {
        int c = d_cnt[i];
        int o = atomicAdd(&d_total, c);
        d_off[i] = o;
        d_cur[i] = o;
    }
}

__global__ void fill_kernel(const int* __restrict__ ei, int E, int n) {
    int e = blockIdx.x * blockDim.x + threadIdx.x;
    if (e < E) {
        int r = ei[e], c = ei[E + e];
        int p = atomicAdd(&d_cur[r], 1);
        d_adj[p] = c;
        int p2 = atomicAdd(&d_cur[n + c], 1);
        d_adj[p2] = r;
    }
}

// ---------------- nodeprep: dinv + emb + n1(layer0) + Wc ----------------
__global__ void __launch_bounds__(256) nodeprep_kernel(
        const float* __restrict__ x, const float* __restrict__ embW,
        const float* __restrict__ embB, const float* __restrict__ gatW,
        const float* __restrict__ attS, const float* __restrict__ attD,
        const float* __restrict__ fusW, const float* __restrict__ e8W,
        int ngrid, int n) {
    if (blockIdx.x >= (unsigned)ngrid) {
        int bid = blockIdx.x - ngrid;
        int gidx = bid * 256 + threadIdx.x;
        if (gidx < 3 * 4096) {
            int layer = gidx >> 12;
            int idx = gidx & 4095;
            int j = idx >> 6, k = idx & 63;
            const float* F = fusW + layer * 64 * 128;
            const float* Ew = e8W + layer * 64 * 64;
            float acc = 0.f;
#pragma unroll
            for (int m = 0; m < 64; m++) acc += F[j * 128 + m] * Ew[m * 64 + k];
            d_Wc[layer * 4096 + j * 64 + k] = acc;
        }
        return;
    }
    __shared__ float We[64 * 65];
    __shared__ float Wg[64 * 65];
    __shared__ float bs[64];
    for (int idx = threadIdx.x; idx < 4096; idx += blockDim.x) {
        int j = idx >> 6, k = idx & 63;
        We[j * 65 + k] = embW[idx];
        Wg[k * 65 + j] = gatW[idx];
    }
    if (threadIdx.x < 64) bs[threadIdx.x] = embB[threadIdx.x];
    __syncthreads();
    int warp = threadIdx.x >> 5, t = threadIdx.x & 31;
    float as0 = attS[t], as1 = attS[t + 32];
    float ad0 = attD[t], ad1 = attD[t + 32];
    for (int node = blockIdx.x * 8 + warp; node < n; node += ngrid * 8) {
        if (t == 0) {
            float dg = (float)d_cnt[n + node];
            d_dinv[node] = dg > 0.f ? rsqrtf(dg) : 0.f;
        }
        float in0 = x[node * 64 + t];
        float in1 = x[node * 64 + t + 32];
        float h0 = bs[t], h1 = bs[t + 32];
#pragma unroll
        for (int k = 0; k < 32; k++) {
            float xk = __shfl_sync(0xffffffffu, in0, k);
            h0 += xk * We[t * 65 + k];
            h1 += xk * We[(t + 32) * 65 + k];
        }
#pragma unroll
        for (int k = 0; k < 32; k++) {
            float xk = __shfl_sync(0xffffffffu, in1, k);
            h0 += xk * We[t * 65 + 32 + k];
            h1 += xk * We[(t + 32) * 65 + 32 + k];
        }
        d_h[node * 64 + t] = h0;
        d_h[node * 64 + t + 32] = h1;
        float g0 = 0.f, g1 = 0.f;
#pragma unroll
        for (int k = 0; k < 32; k++) {
            float xk = __shfl_sync(0xffffffffu, h0, k);
            g0 += xk * Wg[t * 65 + k];
            g1 += xk * Wg[(t + 32) * 65 + k];
        }
#pragma unroll
        for (int k = 0; k < 32; k++) {
            float xk = __shfl_sync(0xffffffffu, h1, k);
            g0 += xk * Wg[t * 65 + 32 + k];
            g1 += xk * Wg[(t + 32) * 65 + 32 + k];
        }
        d_g2[node * 32 + t] = __floats2half2_rn(g0, g1);
        float ps0 = g0 * as0, ps1 = g1 * as1;
        float pd0 = g0 * ad0, pd1 = g1 * ad1;
#pragma unroll
        for (int off = 8; off; off >>= 1) {
            ps0 += __shfl_xor_sync(0xffffffffu, ps0, off);
            ps1 += __shfl_xor_sync(0xffffffffu, ps1, off);
            pd0 += __shfl_xor_sync(0xffffffffu, pd0, off);
            pd1 += __shfl_xor_sync(0xffffffffu, pd1, off);
        }
        if ((t & 15) == 0) {
            int hh = t >> 4;
            d_as[node * 4 + hh] = ps0;
            d_as[node * 4 + 2 + hh] = ps1;
            d_ad[node * 4 + hh] = pd0;
            d_ad[node * 4 + 2 + hh] = pd1;
        }
    }
}

// ---------------- N1 (layers 1,2): single-node GEMV (R5 form), half2 g output ----------------
__global__ void __launch_bounds__(256) n1_kernel(
        const float* __restrict__ gatW, const float* __restrict__ attS,
        const float* __restrict__ attD, int layer, int flip, int n) {
    const float* hin = flip ? d_h2 : d_h;
    __shared__ float Ws[64 * 65];
    const float* W = gatW + layer * 4096;
    for (int idx = threadIdx.x; idx < 4096; idx += blockDim.x) {
        int k = idx >> 6, j = idx & 63;
        Ws[j * 65 + k] = W[idx];
    }
    __syncthreads();
    int warp = threadIdx.x >> 5, t = threadIdx.x & 31;
    float as0 = attS[layer * 64 + t], as1 = attS[layer * 64 + t + 32];
    float ad0 = attD[layer * 64 + t], ad1 = attD[layer * 64 + t + 32];
    for (int node = blockIdx.x * 8 + warp; node < n; node += gridDim.x * 8) {
        float in0 = hin[node * 64 + t], in1 = hin[node * 64 + t + 32];
        float g0 = 0.f, g1 = 0.f;
#pragma unroll
        for (int k = 0; k < 32; k++) {
            float xk = __shfl_sync(0xffffffffu, in0, k);
            g0 += xk * Ws[t * 65 + k];
            g1 += xk * Ws[(t + 32) * 65 + k];
        }
#pragma unroll
        for (int k = 0; k < 32; k++) {
            float xk = __shfl_sync(0xffffffffu, in1, k);
            g0 += xk * Ws[t * 65 + 32 + k];
            g1 += xk * Ws[(t + 32) * 65 + 32 + k];
        }
        d_g2[node * 32 + t] = __floats2half2_rn(g0, g1);
        float ps0 = g0 * as0, ps1 = g1 * as1;
        float pd0 = g0 * ad0, pd1 = g1 * ad1;
#pragma unroll
        for (int off = 8; off; off >>= 1) {
            ps0 += __shfl_xor_sync(0xffffffffu, ps0, off);
            ps1 += __shfl_xor_sync(0xffffffffu, ps1, off);
            pd0 += __shfl_xor_sync(0xffffffffu, pd0, off);
            pd1 += __shfl_xor_sync(0xffffffffu, pd1, off);
        }
        if ((t & 15) == 0) {
            int hh = t >> 4;
            d_as[node * 4 + hh] = ps0;
            d_as[node * 4 + 2 + hh] = ps1;
            d_ad[node * 4 + hh] = pd0;
            d_ad[node * 4 + 2 + hh] = pd1;
        }
    }
}

// ---------------- layer: tile-of-32 nodes; gather -> smem -> register-tiled GEMM -> LN ----------------
// dynamic smem layout (floats):
//   Wt [128][66]  : 8448   (Wt[k][j] = stacked weight, col-major by k)
//   In [128][36]  : 4608   (In[k][node-in-tile])
//   Out[64][36]   : 2304
//   fb, gb, lg, lb: 64 each
#define LK_WT   0
#define LK_IN   8448
#define LK_OUT  13056
#define LK_FB   15360
#define LK_SMEM_FLOATS 15616

__global__ void __launch_bounds__(256) layer_kernel(
        const float* __restrict__ fusW, const float* __restrict__ fusB,
        const float* __restrict__ gatB, const float* __restrict__ lnG,
        const float* __restrict__ lnB, int layer, int flip, int n) {
    extern __shared__ float sm[];
    float* Wt = sm + LK_WT;
    float* In = sm + LK_IN;
    float* Outs = sm + LK_OUT;
    float* fb = sm + LK_FB;
    float* gb = fb + 64;
    float* lg = gb + 64;
    float* lb = lg + 64;

    const float* hin = flip ? d_h2 : d_h;
    float* hout = flip ? d_h : d_h2;
    const float* Wc = d_Wc + layer * 4096;
    const float* F = fusW + layer * 64 * 128;

    // load stacked weights: Wt[k][j] = (k<64) ? Wc[j][k] : fusW_right[j][k-64]
    for (int idx = threadIdx.x; idx < 8192; idx += 256) {
        int k = idx >> 6, j = idx & 63;
        float v = (k < 64) ? Wc[j * 64 + k] : F[j * 128 + 64 + (k - 64)];
        Wt[k * 66 + j] = v;
    }
    if (threadIdx.x < 64) {
        fb[threadIdx.x] = fusB[layer * 64 + threadIdx.x];
        gb[threadIdx.x] = gatB[layer * 64 + threadIdx.x];
        lg[threadIdx.x] = lnG[layer * 64 + threadIdx.x];
        lb[threadIdx.x] = lnB[layer * 64 + threadIdx.x];
    }
    __syncthreads();

    int warp = threadIdx.x >> 5, t = threadIdx.x & 31;
    int hA = t >> 4;
    int tile0 = blockIdx.x * 32;

    // ---------- phase 1: gather (warp w -> tile nodes w*4 .. w*4+3) ----------
    for (int q = 0; q < 4; q++) {
        int ni = warp * 4 + q;
        int node = tile0 + ni;
        float a0 = 0.f, a1 = 0.f, x0v = 0.f, x1v = 0.f;
        if (node < n) {
            // GAT gather (col-CSR)
            float adA = d_ad[node * 4 + hA];
            float adB = d_ad[node * 4 + 2 + hA];
            float eeS0 = __expf(leaky02(d_as[node * 4 + hA] + adA));
            float eeS1 = __expf(leaky02(d_as[node * 4 + 2 + hA] + adB));
            float2 gself = __half22float2(d_g2[node * 32 + t]);
            float w0 = eeS0 * gself.x, w1 = eeS1 * gself.y;
            float s0 = eeS0, s1 = eeS1;
            int beg = d_off[n + node];
            int dc = d_cnt[n + node];
            for (int i = 0; i < dc; i++) {
                int src = __ldg(&d_adj[beg + i]);
                float2 gv = __half22float2(d_g2[src * 32 + t]);
                float ee0 = __expf(leaky02(d_as[src * 4 + hA] + adA));
                float ee1 = __expf(leaky02(d_as[src * 4 + 2 + hA] + adB));
                w0 += ee0 * gv.x;
                w1 += ee1 * gv.y;
                s0 += ee0;
                s1 += ee1;
            }
            x0v = w0 / s0 + gb[t];
            x1v = w1 / s1 + gb[t + 32];
            // E8 gather (row-CSR)
            int beg2 = d_off[node];
            int dr = d_cnt[node];
            for (int i = 0; i < dr; i++) {
                int c = __ldg(&d_adj[beg2 + i]);
                float dv = d_dinv[c];
                a0 += dv * hin[c * 64 + t];
                a1 += dv * hin[c * 64 + t + 32];
            }
            float dvr = d_dinv[node];
            a0 *= dvr;
            a1 *= dvr;
        }
        In[t * 36 + ni] = a0;
        In[(t + 32) * 36 + ni] = a1;
        In[(t + 64) * 36 + ni] = x0v;
        In[(t + 96) * 36 + ni] = x1v;
    }
    __syncthreads();

    // ---------- phase 2: GEMM Out[64,32] = Wt^T(64x128) x In(128x32) ----------
    // warp covers rows [16*(w&3), +16), nodes [16*(w>>2), +16)
    // lane: rowgroup rg = t&7 -> 2 rows; nodegroup ng = t>>3 -> 4 nodes
    {
        int row_base = (warp & 3) * 16;
        int node_base = (warp >> 2) * 16;
        int r0 = row_base + (t & 7) * 2;
        int nb0 = node_base + (t >> 3) * 4;
        float acc00 = fb[r0], acc01 = fb[r0], acc02 = fb[r0], acc03 = fb[r0];
        float acc10 = fb[r0 + 1], acc11 = fb[r0 + 1], acc12 = fb[r0 + 1], acc13 = fb[r0 + 1];
#pragma unroll 4
        for (int k = 0; k < 128; k++) {
            float2 wv = *reinterpret_cast<const float2*>(&Wt[k * 66 + r0]);
            float4 iv = *reinterpret_cast<const float4*>(&In[k * 36 + nb0]);
            acc00 += wv.x * iv.x;
            acc01 += wv.x * iv.y;
            acc02 += wv.x * iv.z;
            acc03 += wv.x * iv.w;
            acc10 += wv.y * iv.x;
            acc11 += wv.y * iv.y;
            acc12 += wv.y * iv.z;
            acc13 += wv.y * iv.w;
        }
        *reinterpret_cast<float4*>(&Outs[r0 * 36 + nb0]) = make_float4(acc00, acc01, acc02, acc03);
        *reinterpret_cast<float4*>(&Outs[(r0 + 1) * 36 + nb0]) = make_float4(acc10, acc11, acc12, acc13);
    }
    __syncthreads();

    // ---------- phase 3: residual + LN + ReLU + store (warp per node) ----------
    for (int q = 0; q < 4; q++) {
        int ni = q * 8 + warp;
        int node = tile0 + ni;
        if (node < n) {
            float c0 = Outs[t * 36 + ni] + hin[node * 64 + t];
            float c1 = Outs[(t + 32) * 36 + ni] + hin[node * 64 + t + 32];
            float ssum = c0 + c1;
#pragma unroll
            for (int off = 16; off; off >>= 1) ssum += __shfl_xor_sync(0xffffffffu, ssum, off);
            float mu = ssum * (1.f / 64.f);
            float dd0 = c0 - mu, dd1 = c1 - mu;
            float vs = dd0 * dd0 + dd1 * dd1;
#pragma unroll
            for (int off = 16; off; off >>= 1) vs += __shfl_xor_sync(0xffffffffu, vs, off);
            float rstd = rsqrtf(vs * (1.f / 64.f) + 1e-5f);
            hout[node * 64 + t] = fmaxf(dd0 * rstd * lg[t] + lb[t], 0.f);
            hout[node * 64 + t + 32] = fmaxf(dd1 * rstd * lg[t + 32] + lb[t + 32], 0.f);
        }
    }
}

// ---------------- readout ----------------
__global__ void readout_kernel(const float* __restrict__ rW1, const float* __restrict__ rb1,
                               const float* __restrict__ rW2, const float* __restrict__ rb2,
                               float* __restrict__ out, int n) {
    const float* hin = d_h2;
    __shared__ float W1s[32 * 65];
    __shared__ float b1s[32], W2s[32];
    for (int idx = threadIdx.x; idx < 2048; idx += blockDim.x) {
        int m = idx >> 6, k = idx & 63;
        W1s[m * 65 + k] = rW1[idx];
    }
    if (threadIdx.x < 32) {
        b1s[threadIdx.x] = rb1[threadIdx.x];
        W2s[threadIdx.x] = rW2[threadIdx.x];
    }
    __syncthreads();
    float b2 = rb2[0];
    int warp = threadIdx.x >> 5, t = threadIdx.x & 31;
    for (int node = blockIdx.x * 8 + warp; node < n; node += gridDim.x * 8) {
        float in0 = hin[node * 64 + t], in1 = hin[node * 64 + t + 32];
        float acc = b1s[t];
#pragma unroll
        for (int k = 0; k < 32; k++) {
            float xk = __shfl_sync(0xffffffffu, in0, k);
            acc += xk * W1s[t * 65 + k];
        }
#pragma unroll
        for (int k = 0; k < 32; k++) {
            float xk = __shfl_sync(0xffffffffu, in1, k);
            acc += xk * W1s[t * 65 + 32 + k];
        }
        acc = fmaxf(acc, 0.f);
        float p = acc * W2s[t];
#pragma unroll
        for (int off = 16; off; off >>= 1) p += __shfl_xor_sync(0xffffffffu, p, off);
        if (t == 0) out[node] = 1.f / (1.f + __expf(-(p + b2)));
    }
}

// ---------------- launch ----------------
extern "C" void kernel_launch(void* const* d_in, const int* in_sizes, int n_in,
                              void* d_out, int out_size) {
    const float* x    = (const float*)d_in[0];
    const int*   ei   = (const int*)d_in[1];
    const float* embW = (const float*)d_in[2];
    const float* embB = (const float*)d_in[3];
    const float* e8W  = (const float*)d_in[4];
    const float* gatW = (const float*)d_in[5];
    const float* attS = (const float*)d_in[6];
    const float* attD = (const float*)d_in[7];
    const float* gatB = (const float*)d_in[8];
    const float* fusW = (const float*)d_in[9];
    const float* fusB = (const float*)d_in[10];
    const float* lnG  = (const float*)d_in[11];
    const float* lnB  = (const float*)d_in[12];
    const float* rW1  = (const float*)d_in[13];
    const float* rb1  = (const float*)d_in[14];
    const float* rW2  = (const float*)d_in[15];
    const float* rb2  = (const float*)d_in[16];
    float* out = (float*)d_out;

    int n = in_sizes[0] / 64;
    int E = in_sizes[1] / 2;
    int n2 = 2 * n;
    int ngrid = 1563;
    int lgrid = (n + 31) / 32;
    const int lsmem = LK_SMEM_FLOATS * 4;   // 62464 bytes

    static int attr_done = 0;
    if (!attr_done) {
        cudaFuncSetAttribute(layer_kernel, cudaFuncAttributeMaxDynamicSharedMemorySize, lsmem);
        attr_done = 1;
    }

    zero_cnt_kernel<<<(n2 + 255) / 256, 256>>>(n2);
    count_kernel<<<(E + 255) / 256, 256>>>(ei, E, n);
    alloc_kernel<<<(n2 + 255) / 256, 256>>>(n2);
    fill_kernel<<<(E + 255) / 256, 256>>>(ei, E, n);
    nodeprep_kernel<<<ngrid + 48, 256>>>(x, embW, embB, gatW, attS, attD, fusW, e8W, ngrid, n);
    layer_kernel<<<lgrid, 256, lsmem>>>(fusW, fusB, gatB, lnG, lnB, 0, 0, n);
    for (int l = 1; l < 3; l++) {
        int flip = l & 1;
        n1_kernel<<<ngrid, 256>>>(gatW, attS, attD, l, flip, n);
        layer_kernel<<<lgrid, 256, lsmem>>>(fusW, fusB, gatB, lnG, lnB, l, flip, n);
    }
    readout_kernel<<<ngrid, 256>>>(rW1, rb1, rW2, rb2, out, n);
}

// round 8
// speedup vs baseline: 1.5646x; 1.4696x over previous
#include <cuda_runtime.h>
#include <cuda_fp16.h>

#define MAXN 100000
#define MAXE 1600000

// ---------------- scratch ----------------
__device__ float d_h[MAXN * 64];
__device__ float d_h2[MAXN * 64];
__device__ __half2 d_g2[MAXN * 32];     // {g[t], g[t+32]} per lane
__device__ float d_as[MAXN * 4];
__device__ float d_ad[MAXN * 4];
__device__ float d_dinv[MAXN];
__device__ float d_Wc[3 * 64 * 64];

__device__ int d_cnt[2 * MAXN];
__device__ int d_off[2 * MAXN];
__device__ int d_cur[2 * MAXN];
__device__ int d_total;
__device__ int d_adj[2 * MAXE];

__device__ __forceinline__ float leaky02(float x) { return x > 0.f ? x : 0.2f * x; }

// ---------------- CSR build ----------------
__global__ void zero_cnt_kernel(int n2) {
    int i = blockIdx.x * blockDim.x + threadIdx.x;
    if (i < n2) d_cnt[i] = 0;
    if (i == 0) d_total = 0;
}

__global__ void count_kernel(const int* __restrict__ ei, int E, int n) {
    int e = blockIdx.x * blockDim.x + threadIdx.x;
    if (e < E) {
        atomicAdd(&d_cnt[ei[e]], 1);
        atomicAdd(&d_cnt[n + ei[E + e]], 1);
    }
}

__global__ void alloc_kernel(int n2) {
    int i = blockIdx.x * blockDim.x + threadIdx.x;
    if (i < n2) {
        int c = d_cnt[i];
        int o = atomicAdd(&d_total, c);
        d_off[i] = o;
        d_cur[i] = o;
    }
}

__global__ void fill_kernel(const int* __restrict__ ei, int E, int n) {
    int e = blockIdx.x * blockDim.x + threadIdx.x;
    if (e < E) {
        int r = ei[e], c = ei[E + e];
        int p = atomicAdd(&d_cur[r], 1);
        d_adj[p] = c;
        int p2 = atomicAdd(&d_cur[n + c], 1);
        d_adj[p2] = r;
    }
}

// ---------------- nodeprep: dinv + emb + n1(layer0) + Wc ----------------
__global__ void __launch_bounds__(256) nodeprep_kernel(
        const float* __restrict__ x, const float* __restrict__ embW,
        const float* __restrict__ embB, const float* __restrict__ gatW,
        const float* __restrict__ attS, const float* __restrict__ attD,
        const float* __restrict__ fusW, const float* __restrict__ e8W,
        int ngrid, int n) {
    if (blockIdx.x >= (unsigned)ngrid) {
        int bid = blockIdx.x - ngrid;
        int gidx = bid * 256 + threadIdx.x;
        if (gidx < 3 * 4096) {
            int layer = gidx >> 12;
            int idx = gidx & 4095;
            int j = idx >> 6, k = idx & 63;
            const float* F = fusW + layer * 64 * 128;
            const float* Ew = e8W + layer * 64 * 64;
            float acc = 0.f;
#pragma unroll
            for (int m = 0; m < 64; m++) acc += F[j * 128 + m] * Ew[m * 64 + k];
            d_Wc[layer * 4096 + j * 64 + k] = acc;
        }
        return;
    }
    __shared__ float We[64 * 65];
    __shared__ float Wg[64 * 65];
    __shared__ float bs[64];
    for (int idx = threadIdx.x; idx < 4096; idx += blockDim.x) {
        int j = idx >> 6, k = idx & 63;
        We[j * 65 + k] = embW[idx];
        Wg[k * 65 + j] = gatW[idx];
    }
    if (threadIdx.x < 64) bs[threadIdx.x] = embB[threadIdx.x];
    __syncthreads();
    int warp = threadIdx.x >> 5, t = threadIdx.x & 31;
    float as0 = attS[t], as1 = attS[t + 32];
    float ad0 = attD[t], ad1 = attD[t + 32];
    for (int node = blockIdx.x * 8 + warp; node < n; node += ngrid * 8) {
        if (t == 0) {
            float dg = (float)d_cnt[n + node];
            d_dinv[node] = dg > 0.f ? rsqrtf(dg) : 0.f;
        }
        float in0 = x[node * 64 + t];
        float in1 = x[node * 64 + t + 32];
        float h0 = bs[t], h1 = bs[t + 32];
#pragma unroll
        for (int k = 0; k < 32; k++) {
            float xk = __shfl_sync(0xffffffffu, in0, k);
            h0 += xk * We[t * 65 + k];
            h1 += xk * We[(t + 32) * 65 + k];
        }
#pragma unroll
        for (int k = 0; k < 32; k++) {
            float xk = __shfl_sync(0xffffffffu, in1, k);
            h0 += xk * We[t * 65 + 32 + k];
            h1 += xk * We[(t + 32) * 65 + 32 + k];
        }
        d_h[node * 64 + t] = h0;
        d_h[node * 64 + t + 32] = h1;
        float g0 = 0.f, g1 = 0.f;
#pragma unroll
        for (int k = 0; k < 32; k++) {
            float xk = __shfl_sync(0xffffffffu, h0, k);
            g0 += xk * Wg[t * 65 + k];
            g1 += xk * Wg[(t + 32) * 65 + k];
        }
#pragma unroll
        for (int k = 0; k < 32; k++) {
            float xk = __shfl_sync(0xffffffffu, h1, k);
            g0 += xk * Wg[t * 65 + 32 + k];
            g1 += xk * Wg[(t + 32) * 65 + 32 + k];
        }
        d_g2[node * 32 + t] = __floats2half2_rn(g0, g1);
        float ps0 = g0 * as0, ps1 = g1 * as1;
        float pd0 = g0 * ad0, pd1 = g1 * ad1;
#pragma unroll
        for (int off = 8; off; off >>= 1) {
            ps0 += __shfl_xor_sync(0xffffffffu, ps0, off);
            ps1 += __shfl_xor_sync(0xffffffffu, ps1, off);
            pd0 += __shfl_xor_sync(0xffffffffu, pd0, off);
            pd1 += __shfl_xor_sync(0xffffffffu, pd1, off);
        }
        if ((t & 15) == 0) {
            int hh = t >> 4;
            d_as[node * 4 + hh] = ps0;
            d_as[node * 4 + 2 + hh] = ps1;
            d_ad[node * 4 + hh] = pd0;
            d_ad[node * 4 + 2 + hh] = pd1;
        }
    }
}

// ---------------- N1 (layers 1,2): R5 single-node GEMV, half2 g output ----------------
__global__ void __launch_bounds__(256) n1_kernel(
        const float* __restrict__ gatW, const float* __restrict__ attS,
        const float* __restrict__ attD, int layer, int flip, int n) {
    const float* hin = flip ? d_h2 : d_h;
    __shared__ float Ws[64 * 65];
    const float* W = gatW + layer * 4096;
    for (int idx = threadIdx.x; idx < 4096; idx += blockDim.x) {
        int k = idx >> 6, j = idx & 63;
        Ws[j * 65 + k] = W[idx];
    }
    __syncthreads();
    int warp = threadIdx.x >> 5, t = threadIdx.x & 31;
    float as0 = attS[layer * 64 + t], as1 = attS[layer * 64 + t + 32];
    float ad0 = attD[layer * 64 + t], ad1 = attD[layer * 64 + t + 32];
    for (int node = blockIdx.x * 8 + warp; node < n; node += gridDim.x * 8) {
        float in0 = hin[node * 64 + t], in1 = hin[node * 64 + t + 32];
        float g0 = 0.f, g1 = 0.f;
#pragma unroll
        for (int k = 0; k < 32; k++) {
            float xk = __shfl_sync(0xffffffffu, in0, k);
            g0 += xk * Ws[t * 65 + k];
            g1 += xk * Ws[(t + 32) * 65 + k];
        }
#pragma unroll
        for (int k = 0; k < 32; k++) {
            float xk = __shfl_sync(0xffffffffu, in1, k);
            g0 += xk * Ws[t * 65 + 32 + k];
            g1 += xk * Ws[(t + 32) * 65 + 32 + k];
        }
        d_g2[node * 32 + t] = __floats2half2_rn(g0, g1);
        float ps0 = g0 * as0, ps1 = g1 * as1;
        float pd0 = g0 * ad0, pd1 = g1 * ad1;
#pragma unroll
        for (int off = 8; off; off >>= 1) {
            ps0 += __shfl_xor_sync(0xffffffffu, ps0, off);
            ps1 += __shfl_xor_sync(0xffffffffu, ps1, off);
            pd0 += __shfl_xor_sync(0xffffffffu, pd0, off);
            pd1 += __shfl_xor_sync(0xffffffffu, pd1, off);
        }
        if ((t & 15) == 0) {
            int hh = t >> 4;
            d_as[node * 4 + hh] = ps0;
            d_as[node * 4 + 2 + hh] = ps1;
            d_ad[node * 4 + hh] = pd0;
            d_ad[node * 4 + 2 + hh] = pd1;
        }
    }
}

// ---------------- layer: R5 structure + half2 g gather + pair-of-2 GEMV ----------------
__global__ void __launch_bounds__(256) layer_kernel(
        const float* __restrict__ fusW, const float* __restrict__ fusB,
        const float* __restrict__ gatB, const float* __restrict__ lnG,
        const float* __restrict__ lnB, int layer, int flip, int n) {
    const float* hin = flip ? d_h2 : d_h;
    float* hout = flip ? d_h : d_h2;
    __shared__ float W1s[64 * 65];
    __shared__ float W2s[64 * 65];
    __shared__ float fb[64], gb[64], lg[64], lb[64];
    const float* Wc = d_Wc + layer * 4096;
    const float* F = fusW + layer * 64 * 128;
    for (int idx = threadIdx.x; idx < 4096; idx += blockDim.x) {
        int j = idx >> 6, k = idx & 63;
        W1s[j * 65 + k] = Wc[idx];
        W2s[j * 65 + k] = F[j * 128 + 64 + k];
    }
    if (threadIdx.x < 64) {
        fb[threadIdx.x] = fusB[layer * 64 + threadIdx.x];
        gb[threadIdx.x] = gatB[layer * 64 + threadIdx.x];
        lg[threadIdx.x] = lnG[layer * 64 + threadIdx.x];
        lb[threadIdx.x] = lnB[layer * 64 + threadIdx.x];
    }
    __syncthreads();
    int warp = threadIdx.x >> 5, t = threadIdx.x & 31;
    int hA = t >> 4;
    int gw = blockIdx.x * 8 + warp;
    int totw = gridDim.x * 8;

    for (int nb = gw * 2; nb < n; nb += totw * 2) {
        // ---------- gathers: node A then node B (independent, no barriers) ----------
        float aA0 = 0.f, aA1 = 0.f, xA0 = 0.f, xA1 = 0.f;
        float aB0 = 0.f, aB1 = 0.f, xB0 = 0.f, xB1 = 0.f;
#pragma unroll
        for (int q = 0; q < 2; q++) {
            int node = nb + q;
            if (node >= n) break;
            // GAT gather (col-CSR), half2 g
            float adA = d_ad[node * 4 + hA];
            float adB = d_ad[node * 4 + 2 + hA];
            float eeS0 = __expf(leaky02(d_as[node * 4 + hA] + adA));
            float eeS1 = __expf(leaky02(d_as[node * 4 + 2 + hA] + adB));
            float2 gself = __half22float2(d_g2[node * 32 + t]);
            float w0 = eeS0 * gself.x, w1 = eeS1 * gself.y;
            float s0 = eeS0, s1 = eeS1;
            int beg = d_off[n + node];
            int dc = d_cnt[n + node];
            for (int i = 0; i < dc; i++) {
                int src = __ldg(&d_adj[beg + i]);
                float2 gv = __half22float2(d_g2[src * 32 + t]);
                float ee0 = __expf(leaky02(d_as[src * 4 + hA] + adA));
                float ee1 = __expf(leaky02(d_as[src * 4 + 2 + hA] + adB));
                w0 += ee0 * gv.x;
                w1 += ee1 * gv.y;
                s0 += ee0;
                s1 += ee1;
            }
            float xx0 = w0 / s0 + gb[t];
            float xx1 = w1 / s1 + gb[t + 32];
            // E8 gather (row-CSR), fp32 h
            float e0 = 0.f, e1 = 0.f;
            int beg2 = d_off[node];
            int dr = d_cnt[node];
            for (int i = 0; i < dr; i++) {
                int c = __ldg(&d_adj[beg2 + i]);
                float dv = d_dinv[c];
                e0 += dv * hin[c * 64 + t];
                e1 += dv * hin[c * 64 + t + 32];
            }
            float dvr = d_dinv[node];
            e0 *= dvr;
            e1 *= dvr;
            if (q == 0) { aA0 = e0; aA1 = e1; xA0 = xx0; xA1 = xx1; }
            else        { aB0 = e0; aB1 = e1; xB0 = xx0; xB1 = xx1; }
        }

        // ---------- joint GEMV for the pair: each weight LDS feeds 4 FMAs ----------
        float accA0 = fb[t], accA1 = fb[t + 32];
        float accB0 = fb[t], accB1 = fb[t + 32];
#pragma unroll
        for (int k = 0; k < 32; k++) {
            float wa = W1s[t * 65 + k], wb = W1s[(t + 32) * 65 + k];
            float vA = __shfl_sync(0xffffffffu, aA0, k);
            float vB = __shfl_sync(0xffffffffu, aB0, k);
            accA0 += vA * wa; accA1 += vA * wb;
            accB0 += vB * wa; accB1 += vB * wb;
        }
#pragma unroll
        for (int k = 0; k < 32; k++) {
            float wa = W1s[t * 65 + 32 + k], wb = W1s[(t + 32) * 65 + 32 + k];
            float vA = __shfl_sync(0xffffffffu, aA1, k);
            float vB = __shfl_sync(0xffffffffu, aB1, k);
            accA0 += vA * wa; accA1 += vA * wb;
            accB0 += vB * wa; accB1 += vB * wb;
        }
#pragma unroll
        for (int k = 0; k < 32; k++) {
            float wa = W2s[t * 65 + k], wb = W2s[(t + 32) * 65 + k];
            float vA = __shfl_sync(0xffffffffu, xA0, k);
            float vB = __shfl_sync(0xffffffffu, xB0, k);
            accA0 += vA * wa; accA1 += vA * wb;
            accB0 += vB * wa; accB1 += vB * wb;
        }
#pragma unroll
        for (int k = 0; k < 32; k++) {
            float wa = W2s[t * 65 + 32 + k], wb = W2s[(t + 32) * 65 + 32 + k];
            float vA = __shfl_sync(0xffffffffu, xA1, k);
            float vB = __shfl_sync(0xffffffffu, xB1, k);
            accA0 += vA * wa; accA1 += vA * wb;
            accB0 += vB * wa; accB1 += vB * wb;
        }

        // ---------- residual + LN + ReLU + store per node ----------
#pragma unroll
        for (int q = 0; q < 2; q++) {
            int node = nb + q;
            if (node >= n) break;
            float c0 = (q == 0 ? accA0 : accB0) + hin[node * 64 + t];
            float c1 = (q == 0 ? accA1 : accB1) + hin[node * 64 + t + 32];
            float ssum = c0 + c1;
#pragma unroll
            for (int off = 16; off; off >>= 1) ssum += __shfl_xor_sync(0xffffffffu, ssum, off);
            float mu = ssum * (1.f / 64.f);
            float dd0 = c0 - mu, dd1 = c1 - mu;
            float vs = dd0 * dd0 + dd1 * dd1;
#pragma unroll
            for (int off = 16; off; off >>= 1) vs += __shfl_xor_sync(0xffffffffu, vs, off);
            float rstd = rsqrtf(vs * (1.f / 64.f) + 1e-5f);
            hout[node * 64 + t] = fmaxf(dd0 * rstd * lg[t] + lb[t], 0.f);
            hout[node * 64 + t + 32] = fmaxf(dd1 * rstd * lg[t + 32] + lb[t + 32], 0.f);
        }
    }
}

// ---------------- readout ----------------
__global__ void readout_kernel(const float* __restrict__ rW1, const float* __restrict__ rb1,
                               const float* __restrict__ rW2, const float* __restrict__ rb2,
                               float* __restrict__ out, int n) {
    const float* hin = d_h2;
    __shared__ float W1s[32 * 65];
    __shared__ float b1s[32], W2s[32];
    for (int idx = threadIdx.x; idx < 2048; idx += blockDim.x) {
        int m = idx >> 6, k = idx & 63;
        W1s[m * 65 + k] = rW1[idx];
    }
    if (threadIdx.x < 32) {
        b1s[threadIdx.x] = rb1[threadIdx.x];
        W2s[threadIdx.x] = rW2[threadIdx.x];
    }
    __syncthreads();
    float b2 = rb2[0];
    int warp = threadIdx.x >> 5, t = threadIdx.x & 31;
    for (int node = blockIdx.x * 8 + warp; node < n; node += gridDim.x * 8) {
        float in0 = hin[node * 64 + t], in1 = hin[node * 64 + t + 32];
        float acc = b1s[t];
#pragma unroll
        for (int k = 0; k < 32; k++) {
            float xk = __shfl_sync(0xffffffffu, in0, k);
            acc += xk * W1s[t * 65 + k];
        }
#pragma unroll
        for (int k = 0; k < 32; k++) {
            float xk = __shfl_sync(0xffffffffu, in1, k);
            acc += xk * W1s[t * 65 + 32 + k];
        }
        acc = fmaxf(acc, 0.f);
        float p = acc * W2s[t];
#pragma unroll
        for (int off = 16; off; off >>= 1) p += __shfl_xor_sync(0xffffffffu, p, off);
        if (t == 0) out[node] = 1.f / (1.f + __expf(-(p + b2)));
    }
}

// ---------------- launch ----------------
extern "C" void kernel_launch(void* const* d_in, const int* in_sizes, int n_in,
                              void* d_out, int out_size) {
    const float* x    = (const float*)d_in[0];
    const int*   ei   = (const int*)d_in[1];
    const float* embW = (const float*)d_in[2];
    const float* embB = (const float*)d_in[3];
    const float* e8W  = (const float*)d_in[4];
    const float* gatW = (const float*)d_in[5];
    const float* attS = (const float*)d_in[6];
    const float* attD = (const float*)d_in[7];
    const float* gatB = (const float*)d_in[8];
    const float* fusW = (const float*)d_in[9];
    const float* fusB = (const float*)d_in[10];
    const float* lnG  = (const float*)d_in[11];
    const float* lnB  = (const float*)d_in[12];
    const float* rW1  = (const float*)d_in[13];
    const float* rb1  = (const float*)d_in[14];
    const float* rW2  = (const float*)d_in[15];
    const float* rb2  = (const float*)d_in[16];
    float* out = (float*)d_out;

    int n = in_sizes[0] / 64;
    int E = in_sizes[1] / 2;
    int n2 = 2 * n;
    int ngrid = 1563;

    zero_cnt_kernel<<<(n2 + 255) / 256, 256>>>(n2);
    count_kernel<<<(E + 255) / 256, 256>>>(ei, E, n);
    alloc_kernel<<<(n2 + 255) / 256, 256>>>(n2);
    fill_kernel<<<(E + 255) / 256, 256>>>(ei, E, n);
    nodeprep_kernel<<<ngrid + 48, 256>>>(x, embW, embB, gatW, attS, attD, fusW, e8W, ngrid, n);
    layer_kernel<<<ngrid, 256>>>(fusW, fusB, gatB, lnG, lnB, 0, 0, n);
    for (int l = 1; l < 3; l++) {
        int flip = l & 1;
        n1_kernel<<<ngrid, 256>>>(gatW, attS, attD, l, flip, n);
        layer_kernel<<<ngrid, 256>>>(fusW, fusB, gatB, lnG, lnB, l, flip, n);
    }
    readout_kernel<<<ngrid, 256>>>(rW1, rb1, rW2, rb2, out, n);
}

// round 9
// speedup vs baseline: 1.7326x; 1.1074x over previous
#include <cuda_runtime.h>
#include <cuda_fp16.h>

#define MAXN 100000
#define MAXE 1600000

// ---------------- scratch ----------------
__device__ float d_h[MAXN * 64];
__device__ float d_h2[MAXN * 64];
__device__ __half2 d_g2[MAXN * 32];     // {g[t], g[t+32]} per lane
__device__ float d_as[MAXN * 4];
__device__ float d_ad[MAXN * 4];
__device__ float d_dinv[MAXN];
__device__ float d_Wc[3 * 64 * 64];

__device__ int d_cnt[2 * MAXN];
__device__ int d_off[2 * MAXN];
__device__ int d_cur[2 * MAXN];
__device__ int d_total;
__device__ int d_adj[2 * MAXE];

__device__ __forceinline__ float leaky02(float x) { return x > 0.f ? x : 0.2f * x; }

// ---------------- CSR build ----------------
__global__ void zero_cnt_kernel(int n2) {
    int i = blockIdx.x * blockDim.x + threadIdx.x;
    if (i < n2) d_cnt[i] = 0;
    if (i == 0) d_total = 0;
}

__global__ void count_kernel(const int* __restrict__ ei, int E, int n) {
    int e = blockIdx.x * blockDim.x + threadIdx.x;
    if (e < E) {
        atomicAdd(&d_cnt[ei[e]], 1);
        atomicAdd(&d_cnt[n + ei[E + e]], 1);
    }
}

__global__ void alloc_kernel(int n2) {
    int i = blockIdx.x * blockDim.x + threadIdx.x;
    if (i < n2) {
        int c = d_cnt[i];
        int o = atomicAdd(&d_total, c);
        d_off[i] = o;
        d_cur[i] = o;
    }
}

__global__ void fill_kernel(const int* __restrict__ ei, int E, int n) {
    int e = blockIdx.x * blockDim.x + threadIdx.x;
    if (e < E) {
        int r = ei[e], c = ei[E + e];
        int p = atomicAdd(&d_cur[r], 1);
        d_adj[p] = c;
        int p2 = atomicAdd(&d_cur[n + c], 1);
        d_adj[p2] = r;
    }
}

// ---------------- nodeprep: dinv + emb + n1(layer0) + Wc ----------------
__global__ void __launch_bounds__(256) nodeprep_kernel(
        const float* __restrict__ x, const float* __restrict__ embW,
        const float* __restrict__ embB, const float* __restrict__ gatW,
        const float* __restrict__ attS, const float* __restrict__ attD,
        const float* __restrict__ fusW, const float* __restrict__ e8W,
        int ngrid, int n) {
    if (blockIdx.x >= (unsigned)ngrid) {
        int bid = blockIdx.x - ngrid;
        int gidx = bid * 256 + threadIdx.x;
        if (gidx < 3 * 4096) {
            int layer = gidx >> 12;
            int idx = gidx & 4095;
            int j = idx >> 6, k = idx & 63;
            const float* F = fusW + layer * 64 * 128;
            const float* Ew = e8W + layer * 64 * 64;
            float acc = 0.f;
#pragma unroll
            for (int m = 0; m < 64; m++) acc += F[j * 128 + m] * Ew[m * 64 + k];
            d_Wc[layer * 4096 + j * 64 + k] = acc;
        }
        return;
    }
    __shared__ float We[64 * 65];
    __shared__ float Wg[64 * 65];
    __shared__ float bs[64];
    for (int idx = threadIdx.x; idx < 4096; idx += blockDim.x) {
        int j = idx >> 6, k = idx & 63;
        We[j * 65 + k] = embW[idx];
        Wg[k * 65 + j] = gatW[idx];
    }
    if (threadIdx.x < 64) bs[threadIdx.x] = embB[threadIdx.x];
    __syncthreads();
    int warp = threadIdx.x >> 5, t = threadIdx.x & 31;
    float as0 = attS[t], as1 = attS[t + 32];
    float ad0 = attD[t], ad1 = attD[t + 32];
    for (int node = blockIdx.x * 8 + warp; node < n; node += ngrid * 8) {
        if (t == 0) {
            float dg = (float)d_cnt[n + node];
            d_dinv[node] = dg > 0.f ? rsqrtf(dg) : 0.f;
        }
        float in0 = x[node * 64 + t];
        float in1 = x[node * 64 + t + 32];
        float h0 = bs[t], h1 = bs[t + 32];
#pragma unroll
        for (int k = 0; k < 32; k++) {
            float xk = __shfl_sync(0xffffffffu, in0, k);
            h0 += xk * We[t * 65 + k];
            h1 += xk * We[(t + 32) * 65 + k];
        }
#pragma unroll
        for (int k = 0; k < 32; k++) {
            float xk = __shfl_sync(0xffffffffu, in1, k);
            h0 += xk * We[t * 65 + 32 + k];
            h1 += xk * We[(t + 32) * 65 + 32 + k];
        }
        d_h[node * 64 + t] = h0;
        d_h[node * 64 + t + 32] = h1;
        float g0 = 0.f, g1 = 0.f;
#pragma unroll
        for (int k = 0; k < 32; k++) {
            float xk = __shfl_sync(0xffffffffu, h0, k);
            g0 += xk * Wg[t * 65 + k];
            g1 += xk * Wg[(t + 32) * 65 + k];
        }
#pragma unroll
        for (int k = 0; k < 32; k++) {
            float xk = __shfl_sync(0xffffffffu, h1, k);
            g0 += xk * Wg[t * 65 + 32 + k];
            g1 += xk * Wg[(t + 32) * 65 + 32 + k];
        }
        d_g2[node * 32 + t] = __floats2half2_rn(g0, g1);
        float ps0 = g0 * as0, ps1 = g1 * as1;
        float pd0 = g0 * ad0, pd1 = g1 * ad1;
#pragma unroll
        for (int off = 8; off; off >>= 1) {
            ps0 += __shfl_xor_sync(0xffffffffu, ps0, off);
            ps1 += __shfl_xor_sync(0xffffffffu, ps1, off);
            pd0 += __shfl_xor_sync(0xffffffffu, pd0, off);
            pd1 += __shfl_xor_sync(0xffffffffu, pd1, off);
        }
        if ((t & 15) == 0) {
            int hh = t >> 4;
            d_as[node * 4 + hh] = ps0;
            d_as[node * 4 + 2 + hh] = ps1;
            d_ad[node * 4 + hh] = pd0;
            d_ad[node * 4 + 2 + hh] = pd1;
        }
    }
}

// ---------------- N1 (layers 1,2): float4-weight GEMV with smem-staged input ----------------
__global__ void __launch_bounds__(256) n1_kernel(
        const float* __restrict__ gatW, const float* __restrict__ attS,
        const float* __restrict__ attD, int layer, int flip, int n) {
    const float* hin = flip ? d_h2 : d_h;
    __shared__ float Wn[64 * 68];   // Wn[j*68+k] = gatW[k][j] (row-major by output j)
    __shared__ float InB[8][64];
    const float* W = gatW + layer * 4096;
    for (int idx = threadIdx.x; idx < 4096; idx += blockDim.x) {
        int k = idx >> 6, j = idx & 63;
        Wn[j * 68 + k] = W[idx];      // W[k*64+j] with idx=k*64+j
    }
    __syncthreads();
    int warp = threadIdx.x >> 5, t = threadIdx.x & 31;
    float as0 = attS[layer * 64 + t], as1 = attS[layer * 64 + t + 32];
    float ad0 = attD[layer * 64 + t], ad1 = attD[layer * 64 + t + 32];
    float* In = InB[warp];
    const float* w0p = &Wn[t * 68];
    const float* w1p = &Wn[(t + 32) * 68];
    for (int node = blockIdx.x * 8 + warp; node < n; node += gridDim.x * 8) {
        In[t] = hin[node * 64 + t];
        In[t + 32] = hin[node * 64 + t + 32];
        __syncwarp();
        float g0 = 0.f, g1 = 0.f;
#pragma unroll
        for (int k4 = 0; k4 < 64; k4 += 4) {
            float4 iv = *reinterpret_cast<const float4*>(&In[k4]);
            float4 w0 = *reinterpret_cast<const float4*>(w0p + k4);
            float4 w1 = *reinterpret_cast<const float4*>(w1p + k4);
            g0 += w0.x * iv.x + w0.y * iv.y + w0.z * iv.z + w0.w * iv.w;
            g1 += w1.x * iv.x + w1.y * iv.y + w1.z * iv.z + w1.w * iv.w;
        }
        __syncwarp();
        d_g2[node * 32 + t] = __floats2half2_rn(g0, g1);
        float ps0 = g0 * as0, ps1 = g1 * as1;
        float pd0 = g0 * ad0, pd1 = g1 * ad1;
#pragma unroll
        for (int off = 8; off; off >>= 1) {
            ps0 += __shfl_xor_sync(0xffffffffu, ps0, off);
            ps1 += __shfl_xor_sync(0xffffffffu, ps1, off);
            pd0 += __shfl_xor_sync(0xffffffffu, pd0, off);
            pd1 += __shfl_xor_sync(0xffffffffu, pd1, off);
        }
        if ((t & 15) == 0) {
            int hh = t >> 4;
            d_as[node * 4 + hh] = ps0;
            d_as[node * 4 + 2 + hh] = ps1;
            d_ad[node * 4 + hh] = pd0;
            d_ad[node * 4 + 2 + hh] = pd1;
        }
    }
}

// ---------------- layer: R8 gathers + smem-staged float4 pair-GEMV ----------------
__global__ void __launch_bounds__(256) layer_kernel(
        const float* __restrict__ fusW, const float* __restrict__ fusB,
        const float* __restrict__ gatB, const float* __restrict__ lnG,
        const float* __restrict__ lnB, int layer, int flip, int n) {
    const float* hin = flip ? d_h2 : d_h;
    float* hout = flip ? d_h : d_h2;
    __shared__ float Wst[64 * 132];   // Wst[j*132+k]: stacked [Wc | fusW_right], k=0..127
    __shared__ float InB[8][256];     // per-warp: [0,128)=node A, [128,256)=node B
    __shared__ float fb[64], gb[64], lg[64], lb[64];
    const float* Wc = d_Wc + layer * 4096;
    const float* F = fusW + layer * 64 * 128;
    for (int idx = threadIdx.x; idx < 8192; idx += 256) {
        int j = idx >> 7, k = idx & 127;
        Wst[j * 132 + k] = (k < 64) ? Wc[j * 64 + k] : F[j * 128 + 64 + (k - 64)];
    }
    if (threadIdx.x < 64) {
        fb[threadIdx.x] = fusB[layer * 64 + threadIdx.x];
        gb[threadIdx.x] = gatB[layer * 64 + threadIdx.x];
        lg[threadIdx.x] = lnG[layer * 64 + threadIdx.x];
        lb[threadIdx.x] = lnB[layer * 64 + threadIdx.x];
    }
    __syncthreads();
    int warp = threadIdx.x >> 5, t = threadIdx.x & 31;
    int hA = t >> 4;
    int gw = blockIdx.x * 8 + warp;
    int totw = gridDim.x * 8;
    float* In = InB[warp];
    const float* w0p = &Wst[t * 132];
    const float* w1p = &Wst[(t + 32) * 132];

    for (int nb = gw * 2; nb < n; nb += totw * 2) {
        // ---------- gathers (R8 form, unchanged) ----------
#pragma unroll
        for (int q = 0; q < 2; q++) {
            int node = nb + q;
            float a0 = 0.f, a1 = 0.f, xx0 = 0.f, xx1 = 0.f;
            if (node < n) {
                float adA = d_ad[node * 4 + hA];
                float adB = d_ad[node * 4 + 2 + hA];
                float eeS0 = __expf(leaky02(d_as[node * 4 + hA] + adA));
                float eeS1 = __expf(leaky02(d_as[node * 4 + 2 + hA] + adB));
                float2 gself = __half22float2(d_g2[node * 32 + t]);
                float w0 = eeS0 * gself.x, w1 = eeS1 * gself.y;
                float s0 = eeS0, s1 = eeS1;
                int beg = d_off[n + node];
                int dc = d_cnt[n + node];
                for (int i = 0; i < dc; i++) {
                    int src = __ldg(&d_adj[beg + i]);
                    float2 gv = __half22float2(d_g2[src * 32 + t]);
                    float ee0 = __expf(leaky02(d_as[src * 4 + hA] + adA));
                    float ee1 = __expf(leaky02(d_as[src * 4 + 2 + hA] + adB));
                    w0 += ee0 * gv.x;
                    w1 += ee1 * gv.y;
                    s0 += ee0;
                    s1 += ee1;
                }
                xx0 = w0 / s0 + gb[t];
                xx1 = w1 / s1 + gb[t + 32];
                float e0 = 0.f, e1 = 0.f;
                int beg2 = d_off[node];
                int dr = d_cnt[node];
                for (int i = 0; i < dr; i++) {
                    int c = __ldg(&d_adj[beg2 + i]);
                    float dv = d_dinv[c];
                    e0 += dv * hin[c * 64 + t];
                    e1 += dv * hin[c * 64 + t + 32];
                }
                float dvr = d_dinv[node];
                a0 = e0 * dvr;
                a1 = e1 * dvr;
            }
            In[q * 128 + t] = a0;
            In[q * 128 + t + 32] = a1;
            In[q * 128 + t + 64] = xx0;
            In[q * 128 + t + 96] = xx1;
        }
        __syncwarp();

        // ---------- pair GEMV: float4 weights + broadcast float4 inputs ----------
        float accA0 = fb[t], accA1 = fb[t + 32];
        float accB0 = fb[t], accB1 = fb[t + 32];
#pragma unroll 8
        for (int k4 = 0; k4 < 128; k4 += 4) {
            float4 w0 = *reinterpret_cast<const float4*>(w0p + k4);
            float4 w1 = *reinterpret_cast<const float4*>(w1p + k4);
            float4 ia = *reinterpret_cast<const float4*>(&In[k4]);
            float4 ib = *reinterpret_cast<const float4*>(&In[128 + k4]);
            accA0 += w0.x * ia.x + w0.y * ia.y + w0.z * ia.z + w0.w * ia.w;
            accA1 += w1.x * ia.x + w1.y * ia.y + w1.z * ia.z + w1.w * ia.w;
            accB0 += w0.x * ib.x + w0.y * ib.y + w0.z * ib.z + w0.w * ib.w;
            accB1 += w1.x * ib.x + w1.y * ib.y + w1.z * ib.z + w1.w * ib.w;
        }
        __syncwarp();

        // ---------- residual + LN + ReLU + store ----------
#pragma unroll
        for (int q = 0; q < 2; q++) {
            int node = nb + q;
            if (node >= n) break;
            float c0 = (q == 0 ? accA0 : accB0) + hin[node * 64 + t];
            float c1 = (q == 0 ? accA1 : accB1) + hin[node * 64 + t + 32];
            float ssum = c0 + c1;
#pragma unroll
            for (int off = 16; off; off >>= 1) ssum += __shfl_xor_sync(0xffffffffu, ssum, off);
            float mu = ssum * (1.f / 64.f);
            float dd0 = c0 - mu, dd1 = c1 - mu;
            float vs = dd0 * dd0 + dd1 * dd1;
#pragma unroll
            for (int off = 16; off; off >>= 1) vs += __shfl_xor_sync(0xffffffffu, vs, off);
            float rstd = rsqrtf(vs * (1.f / 64.f) + 1e-5f);
            hout[node * 64 + t] = fmaxf(dd0 * rstd * lg[t] + lb[t], 0.f);
            hout[node * 64 + t + 32] = fmaxf(dd1 * rstd * lg[t + 32] + lb[t + 32], 0.f);
        }
    }
}

// ---------------- readout ----------------
__global__ void readout_kernel(const float* __restrict__ rW1, const float* __restrict__ rb1,
                               const float* __restrict__ rW2, const float* __restrict__ rb2,
                               float* __restrict__ out, int n) {
    const float* hin = d_h2;
    __shared__ float W1s[32 * 68];
    __shared__ float InB[8][64];
    __shared__ float b1s[32], W2s[32];
    for (int idx = threadIdx.x; idx < 2048; idx += blockDim.x) {
        int m = idx >> 6, k = idx & 63;
        W1s[m * 68 + k] = rW1[idx];
    }
    if (threadIdx.x < 32) {
        b1s[threadIdx.x] = rb1[threadIdx.x];
        W2s[threadIdx.x] = rW2[threadIdx.x];
    }
    __syncthreads();
    float b2 = rb2[0];
    int warp = threadIdx.x >> 5, t = threadIdx.x & 31;
    float* In = InB[warp];
    const float* wp = &W1s[t * 68];
    for (int node = blockIdx.x * 8 + warp; node < n; node += gridDim.x * 8) {
        In[t] = hin[node * 64 + t];
        In[t + 32] = hin[node * 64 + t + 32];
        __syncwarp();
        float acc = b1s[t];
#pragma unroll
        for (int k4 = 0; k4 < 64; k4 += 4) {
            float4 iv = *reinterpret_cast<const float4*>(&In[k4]);
            float4 w = *reinterpret_cast<const float4*>(wp + k4);
            acc += w.x * iv.x + w.y * iv.y + w.z * iv.z + w.w * iv.w;
        }
        __syncwarp();
        acc = fmaxf(acc, 0.f);
        float p = acc * W2s[t];
#pragma unroll
        for (int off = 16; off; off >>= 1) p += __shfl_xor_sync(0xffffffffu, p, off);
        if (t == 0) out[node] = 1.f / (1.f + __expf(-(p + b2)));
    }
}

// ---------------- launch ----------------
extern "C" void kernel_launch(void* const* d_in, const int* in_sizes, int n_in,
                              void* d_out, int out_size) {
    const float* x    = (const float*)d_in[0];
    const int*   ei   = (const int*)d_in[1];
    const float* embW = (const float*)d_in[2];
    const float* embB = (const float*)d_in[3];
    const float* e8W  = (const float*)d_in[4];
    const float* gatW = (const float*)d_in[5];
    const float* attS = (const float*)d_in[6];
    const float* attD = (const float*)d_in[7];
    const float* gatB = (const float*)d_in[8];
    const float* fusW = (const float*)d_in[9];
    const float* fusB = (const float*)d_in[10];
    const float* lnG  = (const float*)d_in[11];
    const float* lnB  = (const float*)d_in[12];
    const float* rW1  = (const float*)d_in[13];
    const float* rb1  = (const float*)d_in[14];
    const float* rW2  = (const float*)d_in[15];
    const float* rb2  = (const float*)d_in[16];
    float* out = (float*)d_out;

    int n = in_sizes[0] / 64;
    int E = in_sizes[1] / 2;
    int n2 = 2 * n;
    int ngrid = 1563;

    zero_cnt_kernel<<<(n2 + 255) / 256, 256>>>(n2);
    count_kernel<<<(E + 255) / 256, 256>>>(ei, E, n);
    alloc_kernel<<<(n2 + 255) / 256, 256>>>(n2);
    fill_kernel<<<(E + 255) / 256, 256>>>(ei, E, n);
    nodeprep_kernel<<<ngrid + 48, 256>>>(x, embW, embB, gatW, attS, attD, fusW, e8W, ngrid, n);
    layer_kernel<<<ngrid, 256>>>(fusW, fusB, gatB, lnG, lnB, 0, 0, n);
    for (int l = 1; l < 3; l++) {
        int flip = l & 1;
        n1_kernel<<<ngrid, 256>>>(gatW, attS, attD, l, flip, n);
        layer_kernel<<<ngrid, 256>>>(fusW, fusB, gatB, lnG, lnB, l, flip, n);
    }
    readout_kernel<<<ngrid, 256>>>(rW1, rb1, rW2, rb2, out, n);
}

// round 10
// speedup vs baseline: 1.7729x; 1.0233x over previous
#include <cuda_runtime.h>
#include <cuda_fp16.h>

#define MAXN 100000
#define MAXE 1600000

// ---------------- scratch ----------------
__device__ float d_h[MAXN * 64];
__device__ float d_h2[MAXN * 64];
__device__ __half2 d_hh[2][MAXN * 32];  // pre-scaled {dinv*h[t], dinv*h[t+32]}, dbl-buffered
__device__ __half2 d_g2[MAXN * 32];     // {g[t], g[t+32]} per lane
__device__ float2 d_asp[MAXN * 2];      // {as[hA], as[hA+2]} for hA=0,1
__device__ float2 d_adp[MAXN * 2];
__device__ float d_dinv[MAXN];
__device__ float d_Wc[3 * 64 * 64];

__device__ int d_cnt[2 * MAXN];
__device__ int d_off[2 * MAXN];
__device__ int d_cur[2 * MAXN];
__device__ int d_total;
__device__ int d_adj[2 * MAXE];

__device__ __forceinline__ float leaky02(float x) { return x > 0.f ? x : 0.2f * x; }

// ---------------- CSR build ----------------
__global__ void zero_cnt_kernel(int n2) {
    int i = blockIdx.x * blockDim.x + threadIdx.x;
    if (i < n2) d_cnt[i] = 0;
    if (i == 0) d_total = 0;
}

__global__ void count_kernel(const int* __restrict__ ei, int E, int n) {
    int e = blockIdx.x * blockDim.x + threadIdx.x;
    if (e < E) {
        atomicAdd(&d_cnt[ei[e]], 1);
        atomicAdd(&d_cnt[n + ei[E + e]], 1);
    }
}

__global__ void alloc_kernel(int n2) {
    int i = blockIdx.x * blockDim.x + threadIdx.x;
    if (i < n2) {
        int c = d_cnt[i];
        int o = atomicAdd(&d_total, c);
        d_off[i] = o;
        d_cur[i] = o;
    }
}

__global__ void fill_kernel(const int* __restrict__ ei, int E, int n) {
    int e = blockIdx.x * blockDim.x + threadIdx.x;
    if (e < E) {
        int r = ei[e], c = ei[E + e];
        int p = atomicAdd(&d_cur[r], 1);
        d_adj[p] = c;
        int p2 = atomicAdd(&d_cur[n + c], 1);
        d_adj[p2] = r;
    }
}

// ---------------- nodeprep: dinv + emb + n1(layer0) + Wc ----------------
__global__ void __launch_bounds__(256) nodeprep_kernel(
        const float* __restrict__ x, const float* __restrict__ embW,
        const float* __restrict__ embB, const float* __restrict__ gatW,
        const float* __restrict__ attS, const float* __restrict__ attD,
        const float* __restrict__ fusW, const float* __restrict__ e8W,
        int ngrid, int n) {
    if (blockIdx.x >= (unsigned)ngrid) {
        int bid = blockIdx.x - ngrid;
        int gidx = bid * 256 + threadIdx.x;
        if (gidx < 3 * 4096) {
            int layer = gidx >> 12;
            int idx = gidx & 4095;
            int j = idx >> 6, k = idx & 63;
            const float* F = fusW + layer * 64 * 128;
            const float* Ew = e8W + layer * 64 * 64;
            float acc = 0.f;
#pragma unroll
            for (int m = 0; m < 64; m++) acc += F[j * 128 + m] * Ew[m * 64 + k];
            d_Wc[layer * 4096 + j * 64 + k] = acc;
        }
        return;
    }
    __shared__ float We[64 * 65];
    __shared__ float Wg[64 * 65];
    __shared__ float bs[64];
    for (int idx = threadIdx.x; idx < 4096; idx += blockDim.x) {
        int j = idx >> 6, k = idx & 63;
        We[j * 65 + k] = embW[idx];
        Wg[k * 65 + j] = gatW[idx];
    }
    if (threadIdx.x < 64) bs[threadIdx.x] = embB[threadIdx.x];
    __syncthreads();
    int warp = threadIdx.x >> 5, t = threadIdx.x & 31;
    float as0 = attS[t], as1 = attS[t + 32];
    float ad0 = attD[t], ad1 = attD[t + 32];
    for (int node = blockIdx.x * 8 + warp; node < n; node += ngrid * 8) {
        float dg = (float)d_cnt[n + node];
        float dvr = dg > 0.f ? rsqrtf(dg) : 0.f;
        if (t == 0) d_dinv[node] = dvr;
        float in0 = x[node * 64 + t];
        float in1 = x[node * 64 + t + 32];
        float h0 = bs[t], h1 = bs[t + 32];
#pragma unroll
        for (int k = 0; k < 32; k++) {
            float xk = __shfl_sync(0xffffffffu, in0, k);
            h0 += xk * We[t * 65 + k];
            h1 += xk * We[(t + 32) * 65 + k];
        }
#pragma unroll
        for (int k = 0; k < 32; k++) {
            float xk = __shfl_sync(0xffffffffu, in1, k);
            h0 += xk * We[t * 65 + 32 + k];
            h1 += xk * We[(t + 32) * 65 + 32 + k];
        }
        d_h[node * 64 + t] = h0;
        d_h[node * 64 + t + 32] = h1;
        d_hh[0][node * 32 + t] = __floats2half2_rn(dvr * h0, dvr * h1);
        float g0 = 0.f, g1 = 0.f;
#pragma unroll
        for (int k = 0; k < 32; k++) {
            float xk = __shfl_sync(0xffffffffu, h0, k);
            g0 += xk * Wg[t * 65 + k];
            g1 += xk * Wg[(t + 32) * 65 + k];
        }
#pragma unroll
        for (int k = 0; k < 32; k++) {
            float xk = __shfl_sync(0xffffffffu, h1, k);
            g0 += xk * Wg[t * 65 + 32 + k];
            g1 += xk * Wg[(t + 32) * 65 + 32 + k];
        }
        d_g2[node * 32 + t] = __floats2half2_rn(g0, g1);
        float ps0 = g0 * as0, ps1 = g1 * as1;
        float pd0 = g0 * ad0, pd1 = g1 * ad1;
#pragma unroll
        for (int off = 8; off; off >>= 1) {
            ps0 += __shfl_xor_sync(0xffffffffu, ps0, off);
            ps1 += __shfl_xor_sync(0xffffffffu, ps1, off);
            pd0 += __shfl_xor_sync(0xffffffffu, pd0, off);
            pd1 += __shfl_xor_sync(0xffffffffu, pd1, off);
        }
        if ((t & 15) == 0) {
            int hh = t >> 4;
            d_asp[node * 2 + hh] = make_float2(ps0, ps1);
            d_adp[node * 2 + hh] = make_float2(pd0, pd1);
        }
    }
}

// ---------------- N1 (layers 1,2): float4-weight GEMV with smem-staged input ----------------
__global__ void __launch_bounds__(256) n1_kernel(
        const float* __restrict__ gatW, const float* __restrict__ attS,
        const float* __restrict__ attD, int layer, int flip, int n) {
    const float* hin = flip ? d_h2 : d_h;
    __shared__ float Wn[64 * 68];
    __shared__ float InB[8][64];
    const float* W = gatW + layer * 4096;
    for (int idx = threadIdx.x; idx < 4096; idx += blockDim.x) {
        int k = idx >> 6, j = idx & 63;
        Wn[j * 68 + k] = W[idx];
    }
    __syncthreads();
    int warp = threadIdx.x >> 5, t = threadIdx.x & 31;
    float as0 = attS[layer * 64 + t], as1 = attS[layer * 64 + t + 32];
    float ad0 = attD[layer * 64 + t], ad1 = attD[layer * 64 + t + 32];
    float* In = InB[warp];
    const float* w0p = &Wn[t * 68];
    const float* w1p = &Wn[(t + 32) * 68];
    for (int node = blockIdx.x * 8 + warp; node < n; node += gridDim.x * 8) {
        In[t] = hin[node * 64 + t];
        In[t + 32] = hin[node * 64 + t + 32];
        __syncwarp();
        float g0 = 0.f, g1 = 0.f;
#pragma unroll
        for (int k4 = 0; k4 < 64; k4 += 4) {
            float4 iv = *reinterpret_cast<const float4*>(&In[k4]);
            float4 w0 = *reinterpret_cast<const float4*>(w0p + k4);
            float4 w1 = *reinterpret_cast<const float4*>(w1p + k4);
            g0 += w0.x * iv.x + w0.y * iv.y + w0.z * iv.z + w0.w * iv.w;
            g1 += w1.x * iv.x + w1.y * iv.y + w1.z * iv.z + w1.w * iv.w;
        }
        __syncwarp();
        d_g2[node * 32 + t] = __floats2half2_rn(g0, g1);
        float ps0 = g0 * as0, ps1 = g1 * as1;
        float pd0 = g0 * ad0, pd1 = g1 * ad1;
#pragma unroll
        for (int off = 8; off; off >>= 1) {
            ps0 += __shfl_xor_sync(0xffffffffu, ps0, off);
            ps1 += __shfl_xor_sync(0xffffffffu, ps1, off);
            pd0 += __shfl_xor_sync(0xffffffffu, pd0, off);
            pd1 += __shfl_xor_sync(0xffffffffu, pd1, off);
        }
        if ((t & 15) == 0) {
            int hh = t >> 4;
            d_asp[node * 2 + hh] = make_float2(ps0, ps1);
            d_adp[node * 2 + hh] = make_float2(pd0, pd1);
        }
    }
}

// ---------------- layer: lean gathers + smem-staged float4 pair-GEMV ----------------
__global__ void __launch_bounds__(256) layer_kernel(
        const float* __restrict__ fusW, const float* __restrict__ fusB,
        const float* __restrict__ gatB, const float* __restrict__ lnG,
        const float* __restrict__ lnB, int layer, int flip, int n) {
    const float* hin = flip ? d_h2 : d_h;
    float* hout = flip ? d_h : d_h2;
    const __half2* hhin = d_hh[flip];
    __half2* hhout = d_hh[flip ^ 1];
    __shared__ float Wst[64 * 132];
    __shared__ float InB[8][256];
    __shared__ float fb[64], gb[64], lg[64], lb[64];
    const float* Wc = d_Wc + layer * 4096;
    const float* F = fusW + layer * 64 * 128;
    for (int idx = threadIdx.x; idx < 8192; idx += 256) {
        int j = idx >> 7, k = idx & 127;
        Wst[j * 132 + k] = (k < 64) ? Wc[j * 64 + k] : F[j * 128 + 64 + (k - 64)];
    }
    if (threadIdx.x < 64) {
        fb[threadIdx.x] = fusB[layer * 64 + threadIdx.x];
        gb[threadIdx.x] = gatB[layer * 64 + threadIdx.x];
        lg[threadIdx.x] = lnG[layer * 64 + threadIdx.x];
        lb[threadIdx.x] = lnB[layer * 64 + threadIdx.x];
    }
    __syncthreads();
    int warp = threadIdx.x >> 5, t = threadIdx.x & 31;
    int hA = t >> 4;
    int gw = blockIdx.x * 8 + warp;
    int totw = gridDim.x * 8;
    float* In = InB[warp];
    const float* w0p = &Wst[t * 132];
    const float* w1p = &Wst[(t + 32) * 132];

    for (int nb = gw * 2; nb < n; nb += totw * 2) {
        // ---------- gathers ----------
#pragma unroll
        for (int q = 0; q < 2; q++) {
            int node = nb + q;
            float a0 = 0.f, a1 = 0.f, xx0 = 0.f, xx1 = 0.f;
            if (node < n) {
                // GAT gather (col-CSR), half2 g, packed logits
                float2 adv = d_adp[node * 2 + hA];
                float2 asn = d_asp[node * 2 + hA];
                float eeS0 = __expf(leaky02(asn.x + adv.x));
                float eeS1 = __expf(leaky02(asn.y + adv.y));
                float2 gself = __half22float2(d_g2[node * 32 + t]);
                float w0 = eeS0 * gself.x, w1 = eeS1 * gself.y;
                float s0 = eeS0, s1 = eeS1;
                int beg = d_off[n + node];
                int dc = d_cnt[n + node];
                for (int i = 0; i < dc; i++) {
                    int src = __ldg(&d_adj[beg + i]);
                    float2 gv = __half22float2(d_g2[src * 32 + t]);
                    float2 asv = __ldg(&d_asp[src * 2 + hA]);
                    float ee0 = __expf(leaky02(asv.x + adv.x));
                    float ee1 = __expf(leaky02(asv.y + adv.y));
                    w0 += ee0 * gv.x;
                    w1 += ee1 * gv.y;
                    s0 += ee0;
                    s1 += ee1;
                }
                xx0 = w0 / s0 + gb[t];
                xx1 = w1 / s1 + gb[t + 32];
                // E8 gather (row-CSR): pre-scaled half2 h
                float e0 = 0.f, e1 = 0.f;
                int beg2 = d_off[node];
                int dr = d_cnt[node];
                for (int i = 0; i < dr; i++) {
                    int c = __ldg(&d_adj[beg2 + i]);
                    float2 hv = __half22float2(hhin[c * 32 + t]);
                    e0 += hv.x;
                    e1 += hv.y;
                }
                float dvr = d_dinv[node];
                a0 = e0 * dvr;
                a1 = e1 * dvr;
            }
            In[q * 128 + t] = a0;
            In[q * 128 + t + 32] = a1;
            In[q * 128 + t + 64] = xx0;
            In[q * 128 + t + 96] = xx1;
        }
        __syncwarp();

        // ---------- pair GEMV: float4 weights + broadcast float4 inputs ----------
        float accA0 = fb[t], accA1 = fb[t + 32];
        float accB0 = fb[t], accB1 = fb[t + 32];
#pragma unroll 8
        for (int k4 = 0; k4 < 128; k4 += 4) {
            float4 w0 = *reinterpret_cast<const float4*>(w0p + k4);
            float4 w1 = *reinterpret_cast<const float4*>(w1p + k4);
            float4 ia = *reinterpret_cast<const float4*>(&In[k4]);
            float4 ib = *reinterpret_cast<const float4*>(&In[128 + k4]);
            accA0 += w0.x * ia.x + w0.y * ia.y + w0.z * ia.z + w0.w * ia.w;
            accA1 += w1.x * ia.x + w1.y * ia.y + w1.z * ia.z + w1.w * ia.w;
            accB0 += w0.x * ib.x + w0.y * ib.y + w0.z * ib.z + w0.w * ib.w;
            accB1 += w1.x * ib.x + w1.y * ib.y + w1.z * ib.z + w1.w * ib.w;
        }
        __syncwarp();

        // ---------- residual + LN + ReLU + store ----------
#pragma unroll
        for (int q = 0; q < 2; q++) {
            int node = nb + q;
            if (node >= n) break;
            float c0 = (q == 0 ? accA0 : accB0) + hin[node * 64 + t];
            float c1 = (q == 0 ? accA1 : accB1) + hin[node * 64 + t + 32];
            float ssum = c0 + c1;
#pragma unroll
            for (int off = 16; off; off >>= 1) ssum += __shfl_xor_sync(0xffffffffu, ssum, off);
            float mu = ssum * (1.f / 64.f);
            float dd0 = c0 - mu, dd1 = c1 - mu;
            float vs = dd0 * dd0 + dd1 * dd1;
#pragma unroll
            for (int off = 16; off; off >>= 1) vs += __shfl_xor_sync(0xffffffffu, vs, off);
            float rstd = rsqrtf(vs * (1.f / 64.f) + 1e-5f);
            float o0 = fmaxf(dd0 * rstd * lg[t] + lb[t], 0.f);
            float o1 = fmaxf(dd1 * rstd * lg[t + 32] + lb[t + 32], 0.f);
            hout[node * 64 + t] = o0;
            hout[node * 64 + t + 32] = o1;
            float dvr = d_dinv[node];
            hhout[node * 32 + t] = __floats2half2_rn(dvr * o0, dvr * o1);
        }
    }
}

// ---------------- readout ----------------
__global__ void readout_kernel(const float* __restrict__ rW1, const float* __restrict__ rb1,
                               const float* __restrict__ rW2, const float* __restrict__ rb2,
                               float* __restrict__ out, int n) {
    const float* hin = d_h2;
    __shared__ float W1s[32 * 68];
    __shared__ float InB[8][64];
    __shared__ float b1s[32], W2s[32];
    for (int idx = threadIdx.x; idx < 2048; idx += blockDim.x) {
        int m = idx >> 6, k = idx & 63;
        W1s[m * 68 + k] = rW1[idx];
    }
    if (threadIdx.x < 32) {
        b1s[threadIdx.x] = rb1[threadIdx.x];
        W2s[threadIdx.x] = rW2[threadIdx.x];
    }
    __syncthreads();
    float b2 = rb2[0];
    int warp = threadIdx.x >> 5, t = threadIdx.x & 31;
    float* In = InB[warp];
    const float* wp = &W1s[t * 68];
    for (int node = blockIdx.x * 8 + warp; node < n; node += gridDim.x * 8) {
        In[t] = hin[node * 64 + t];
        In[t + 32] = hin[node * 64 + t + 32];
        __syncwarp();
        float acc = b1s[t];
#pragma unroll
        for (int k4 = 0; k4 < 64; k4 += 4) {
            float4 iv = *reinterpret_cast<const float4*>(&In[k4]);
            float4 w = *reinterpret_cast<const float4*>(wp + k4);
            acc += w.x * iv.x + w.y * iv.y + w.z * iv.z + w.w * iv.w;
        }
        __syncwarp();
        acc = fmaxf(acc, 0.f);
        float p = acc * W2s[t];
#pragma unroll
        for (int off = 16; off; off >>= 1) p += __shfl_xor_sync(0xffffffffu, p, off);
        if (t == 0) out[node] = 1.f / (1.f + __expf(-(p + b2)));
    }
}

// ---------------- launch ----------------
extern "C" void kernel_launch(void* const* d_in, const int* in_sizes, int n_in,
                              void* d_out, int out_size) {
    const float* x    = (const float*)d_in[0];
    const int*   ei   = (const int*)d_in[1];
    const float* embW = (const float*)d_in[2];
    const float* embB = (const float*)d_in[3];
    const float* e8W  = (const float*)d_in[4];
    const float* gatW = (const float*)d_in[5];
    const float* attS = (const float*)d_in[6];
    const float* attD = (const float*)d_in[7];
    const float* gatB = (const float*)d_in[8];
    const float* fusW = (const float*)d_in[9];
    const float* fusB = (const float*)d_in[10];
    const float* lnG  = (const float*)d_in[11];
    const float* lnB  = (const float*)d_in[12];
    const float* rW1  = (const float*)d_in[13];
    const float* rb1  = (const float*)d_in[14];
    const float* rW2  = (const float*)d_in[15];
    const float* rb2  = (const float*)d_in[16];
    float* out = (float*)d_out;

    int n = in_sizes[0] / 64;
    int E = in_sizes[1] / 2;
    int n2 = 2 * n;
    int ngrid = 1563;

    zero_cnt_kernel<<<(n2 + 255) / 256, 256>>>(n2);
    count_kernel<<<(E + 255) / 256, 256>>>(ei, E, n);
    alloc_kernel<<<(n2 + 255) / 256, 256>>>(n2);
    fill_kernel<<<(E + 255) / 256, 256>>>(ei, E, n);
    nodeprep_kernel<<<ngrid + 48, 256>>>(x, embW, embB, gatW, attS, attD, fusW, e8W, ngrid, n);
    layer_kernel<<<ngrid, 256>>>(fusW, fusB, gatB, lnG, lnB, 0, 0, n);
    for (int l = 1; l < 3; l++) {
        int flip = l & 1;
        n1_kernel<<<ngrid, 256>>>(gatW, attS, attD, l, flip, n);
        layer_kernel<<<ngrid, 256>>>(fusW, fusB, gatB, lnG, lnB, l, flip, n);
    }
    readout_kernel<<<ngrid, 256>>>(rW1, rb1, rW2, rb2, out, n);
}